// round 11
// baseline (speedup 1.0000x reference)
#include <cuda_runtime.h>
#include <cuda_fp16.h>
#include <cstdint>

#define NB 8192
#define FD 4096
#define NH 16
#define HI 256
#define HO 1024
#define MD 16384

// Scratch (device globals — no allocation in kernel_launch)
__device__ __half g_xperm[NB * FD];                 // 64 MB
__device__ __half g_w1[NH * HI * HO];               // 8 MB  [h][k=HI][n=HO]
__device__ __half g_w2[NH * HO * HI];               // 8 MB  [h][k=HO][n=HI]
__device__ __half g_h[(long long)NB * MD];          // 256 MB

__device__ __forceinline__ float gelu_f(float v) {
    return 0.5f * v * (1.0f + erff(v * 0.7071067811865476f));
}

__device__ __forceinline__ void ldsm4(unsigned &r0, unsigned &r1, unsigned &r2, unsigned &r3, unsigned addr) {
    asm volatile("ldmatrix.sync.aligned.m8n8.x4.shared.b16 {%0,%1,%2,%3},[%4];"
                 : "=r"(r0), "=r"(r1), "=r"(r2), "=r"(r3) : "r"(addr));
}
__device__ __forceinline__ void ldsm4t(unsigned &r0, unsigned &r1, unsigned &r2, unsigned &r3, unsigned addr) {
    asm volatile("ldmatrix.sync.aligned.m8n8.x4.trans.shared.b16 {%0,%1,%2,%3},[%4];"
                 : "=r"(r0), "=r"(r1), "=r"(r2), "=r"(r3) : "r"(addr));
}
__device__ __forceinline__ void mma16816(float c[4], const unsigned a[4], const unsigned b[2]) {
    asm volatile("mma.sync.aligned.m16n8k16.row.col.f32.f16.f16.f32 "
                 "{%0,%1,%2,%3},{%4,%5,%6,%7},{%8,%9},{%0,%1,%2,%3};"
                 : "+f"(c[0]), "+f"(c[1]), "+f"(c[2]), "+f"(c[3])
                 : "r"(a[0]), "r"(a[1]), "r"(a[2]), "r"(a[3]), "r"(b[0]), "r"(b[1]));
}

#define CP16(s, g) asm volatile("cp.async.cg.shared.global [%0], [%1], 16;\n" :: "r"(s), "l"(g))

// ---------------------------------------------------------------------------
// Prep kernels (identical to the R8 passing kernel)
// ---------------------------------------------------------------------------
__global__ void __launch_bounds__(256) k_prep_x(const float* __restrict__ x,
                                                const int* __restrict__ perm) {
    int i = blockIdx.x * 256 + threadIdx.x;
    if (i >= NB * FD / 4) return;
    int b  = i >> 10;
    int k4 = (i & 1023) << 2;
    int p  = __ldg(perm + k4);
    const float4 v = *(const float4*)(x + (long long)b * FD + p);
    __half2* dst = (__half2*)(g_xperm + (long long)b * FD + k4);
    dst[0] = __floats2half2_rn(v.x, v.y);
    dst[1] = __floats2half2_rn(v.z, v.w);
}

__global__ void __launch_bounds__(256) k_prep_w(const float* __restrict__ wu,
                                                const float* __restrict__ wd) {
    int i = blockIdx.x * 256 + threadIdx.x;
    const int N4 = NH * HI * HO / 4;
    if (i >= N4) return;
    float4 a = *(const float4*)(wu + (long long)i * 4);
    __half2* d1 = (__half2*)(g_w1 + (long long)i * 4);
    d1[0] = __floats2half2_rn(a.x, a.y);
    d1[1] = __floats2half2_rn(a.z, a.w);
    float4 b = *(const float4*)(wd + (long long)i * 4);
    __half2* d2 = (__half2*)(g_w2 + (long long)i * 4);
    d2[0] = __floats2half2_rn(b.x, b.y);
    d2[1] = __floats2half2_rn(b.z, b.w);
}

// ---------------------------------------------------------------------------
// GEMM: CTA tile 256x128 (BM=256, BN=128, BK=64), 8 warps 4x2, warp tile 64x64.
// 3-stage cp.async, XOR-swizzled smem, trans-ldmatrix for B from [k][n] weights.
// Identical structure to the validated R8 kernel except BM 128->256 (mi 2->4).
//   EPI=0: g_h = gelu(Xperm @ W1 + b_up)   (fp16)
//   EPI=1: out[:, perm[j]] = H @ W2 + b_down  (fp32 scatter)
// ---------------------------------------------------------------------------
template<int KT, int NT_BITS, int LDA, int LDB, int EPI>
__global__ void __launch_bounds__(256) gemm_k(const float* __restrict__ bias,
                                              const int* __restrict__ perm,
                                              float* __restrict__ out) {
    extern __shared__ char smem[];
    constexpr int ASTG = 256 * 128;   // 32 KB per A stage (256 rows x 128 B)
    constexpr int BSTG = 64 * 256;    // 16 KB per B stage (64 k-rows x 256 B)
    constexpr int AHEAD = KT * 64;    // per-head K
    const unsigned sAb = (unsigned)__cvta_generic_to_shared(smem);
    const unsigned sBb = sAb + 3 * ASTG;

    const int h  = blockIdx.x >> NT_BITS;
    const int nt = blockIdx.x & ((1 << NT_BITS) - 1);
    const int r0 = blockIdx.y << 8;
    const int n0 = nt << 7;
    const int tid = threadIdx.x;
    const int lane = tid & 31, warp = tid >> 5;
    const int wm = warp & 3, wn = warp >> 2;

    const __half* Ag = (EPI == 0 ? g_xperm : g_h) + (long long)r0 * LDA + h * AHEAD;
    const __half* Bg = (EPI == 0 ? g_w1 : g_w2) + (long long)h * AHEAD * LDB + n0;

    auto load_stage = [&](int stage, int kt) {
        const unsigned sa = sAb + stage * ASTG;
        const unsigned sb = sBb + stage * BSTG;
        const __half* Agk = Ag + kt * 64;
        const __half* Bgk = Bg + (long long)kt * 64 * LDB;
#pragma unroll
        for (int i = 0; i < 8; i++) {
            int c = tid + i * 256;
            int m = c >> 3, g = c & 7;
            CP16(sa + m * 128 + ((g ^ (m & 7)) << 4), Agk + (long long)m * LDA + g * 8);
        }
#pragma unroll
        for (int i = 0; i < 4; i++) {
            int c = tid + i * 256;
            int k = c >> 4, cn = c & 15;
            CP16(sb + k * 256 + ((cn ^ ((k & 7) << 1)) << 4), Bgk + (long long)k * LDB + cn * 8);
        }
        asm volatile("cp.async.commit_group;\n");
    };

    float acc[4][8][4] = {};

    load_stage(0, 0);

    for (int kt = 0; kt < KT; kt++) {
        if (kt + 1 < KT) {
            load_stage((kt + 1) % 3, kt + 1);
            asm volatile("cp.async.wait_group 1;\n");
        } else {
            asm volatile("cp.async.wait_group 0;\n");
        }
        __syncthreads();
        const int stg = kt % 3;
        const unsigned sa = sAb + stg * ASTG;
        const unsigned sb = sBb + stg * BSTG;
#pragma unroll
        for (int ks = 0; ks < 4; ks++) {
            const int k16 = ks * 2 + (lane >> 4);
            unsigned af[4][4];
#pragma unroll
            for (int mi = 0; mi < 4; mi++) {
                int m = wm * 64 + mi * 16 + (lane & 15);
                ldsm4(af[mi][0], af[mi][1], af[mi][2], af[mi][3],
                      sa + m * 128 + ((k16 ^ (m & 7)) << 4));
            }
            unsigned bf[8][2];
#pragma unroll
            for (int nj = 0; nj < 4; nj++) {
                int k = ks * 16 + (lane & 15);
                int cn = wn * 8 + nj * 2 + (lane >> 4);
                unsigned t0, t1, t2, t3;
                ldsm4t(t0, t1, t2, t3, sb + k * 256 + ((cn ^ ((k & 7) << 1)) << 4));
                bf[nj * 2][0] = t0; bf[nj * 2][1] = t1;
                bf[nj * 2 + 1][0] = t2; bf[nj * 2 + 1][1] = t3;
            }
#pragma unroll
            for (int mi = 0; mi < 4; mi++)
#pragma unroll
                for (int ni = 0; ni < 8; ni++)
                    mma16816(acc[mi][ni], af[mi], bf[ni]);
        }
        // 3 stages, prefetch distance 1: writer at kt targets (kt+1)%3; active
        // reader kt%3; laggard reader (kt-1)%3 — all distinct mod 3.
    }

    // Epilogue (identical math to R8; mi range extended to 4)
    const int g = lane >> 2, t = lane & 3;
    const int cb = h * LDB + n0;
#pragma unroll
    for (int mi = 0; mi < 4; mi++) {
#pragma unroll
        for (int ni = 0; ni < 8; ni++) {
            int r = r0 + wm * 64 + mi * 16 + g;
            int c = cb + wn * 64 + ni * 8 + t * 2;
            float b0 = __ldg(bias + c), b1 = __ldg(bias + c + 1);
            if (EPI == 0) {
                float v0 = gelu_f(acc[mi][ni][0] + b0);
                float v1 = gelu_f(acc[mi][ni][1] + b1);
                *(__half2*)(g_h + (long long)r * MD + c) = __floats2half2_rn(v0, v1);
                v0 = gelu_f(acc[mi][ni][2] + b0);
                v1 = gelu_f(acc[mi][ni][3] + b1);
                *(__half2*)(g_h + (long long)(r + 8) * MD + c) = __floats2half2_rn(v0, v1);
            } else {
                int p = __ldg(perm + c);   // c even; 64-chunk perm => perm[c+1]=perm[c]+1
                float2 o0; o0.x = acc[mi][ni][0] + b0; o0.y = acc[mi][ni][1] + b1;
                *(float2*)(out + (long long)r * FD + p) = o0;
                float2 o1; o1.x = acc[mi][ni][2] + b0; o1.y = acc[mi][ni][3] + b1;
                *(float2*)(out + (long long)(r + 8) * FD + p) = o1;
            }
        }
    }
}

extern "C" void kernel_launch(void* const* d_in, const int* in_sizes, int n_in,
                              void* d_out, int out_size) {
    const float* x      = (const float*)d_in[0];
    const int*   perm   = (const int*)d_in[1];
    const float* w_up   = (const float*)d_in[2];
    const float* b_up   = (const float*)d_in[3];
    const float* w_down = (const float*)d_in[4];
    const float* b_down = (const float*)d_in[5];
    float* out = (float*)d_out;

    k_prep_x<<<(NB * FD / 4 + 255) / 256, 256>>>(x, perm);
    k_prep_w<<<(NH * HI * HO / 4 + 255) / 256, 256>>>(w_up, w_down);

    constexpr int SMEM = 3 * (256 * 128 + 64 * 256);   // 147456 bytes
    cudaFuncSetAttribute(gemm_k<4, 3, FD, HO, 0>,
                         cudaFuncAttributeMaxDynamicSharedMemorySize, SMEM);
    cudaFuncSetAttribute(gemm_k<16, 1, MD, HI, 1>,
                         cudaFuncAttributeMaxDynamicSharedMemorySize, SMEM);

    dim3 g1(NH * 8, NB / 256);   // (128, 32): K=256
    gemm_k<4, 3, FD, HO, 0><<<g1, 256, SMEM>>>(b_up, perm, (float*)nullptr);

    dim3 g2(NH * 2, NB / 256);   // (32, 32): K=1024
    gemm_k<16, 1, MD, HI, 1><<<g2, 256, SMEM>>>(b_down, perm, out);
}

// round 12
// speedup vs baseline: 1.1030x; 1.1030x over previous
#include <cuda_runtime.h>
#include <cuda_fp16.h>
#include <cstdint>

#define NB 8192
#define FD 4096
#define NH 16
#define HI 256
#define HO 1024
#define MD 16384

// Scratch (device globals — no allocation in kernel_launch)
__device__ __half g_xperm[NB * FD];                 // 64 MB
__device__ __half g_w1[NH * HI * HO];               // 8 MB  [h][k=HI][n=HO]
__device__ __half g_w2[NH * HO * HI];               // 8 MB  [h][k=HO][n=HI]
__device__ __half g_h[(long long)NB * MD];          // 256 MB

__device__ __forceinline__ float gelu_f(float v) {
    return 0.5f * v * (1.0f + erff(v * 0.7071067811865476f));
}
__device__ __forceinline__ void ldsm4(unsigned &r0, unsigned &r1, unsigned &r2, unsigned &r3, unsigned addr) {
    asm volatile("ldmatrix.sync.aligned.m8n8.x4.shared.b16 {%0,%1,%2,%3},[%4];"
                 : "=r"(r0), "=r"(r1), "=r"(r2), "=r"(r3) : "r"(addr));
}
__device__ __forceinline__ void ldsm4t(unsigned &r0, unsigned &r1, unsigned &r2, unsigned &r3, unsigned addr) {
    asm volatile("ldmatrix.sync.aligned.m8n8.x4.trans.shared.b16 {%0,%1,%2,%3},[%4];"
                 : "=r"(r0), "=r"(r1), "=r"(r2), "=r"(r3) : "r"(addr));
}
__device__ __forceinline__ void mma16816(float c[4], const unsigned a[4], const unsigned b[2]) {
    asm volatile("mma.sync.aligned.m16n8k16.row.col.f32.f16.f16.f32 "
                 "{%0,%1,%2,%3},{%4,%5,%6,%7},{%8,%9},{%0,%1,%2,%3};"
                 : "+f"(c[0]), "+f"(c[1]), "+f"(c[2]), "+f"(c[3])
                 : "r"(a[0]), "r"(a[1]), "r"(a[2]), "r"(a[3]), "r"(b[0]), "r"(b[1]));
}
#define CP16(s, g) asm volatile("cp.async.cg.shared.global [%0], [%1], 16;\n" :: "r"(s), "l"(g))

// ---------------------------------------------------------------------------
// Prep kernels (unchanged, validated)
// ---------------------------------------------------------------------------
__global__ void __launch_bounds__(256) k_prep_x(const float* __restrict__ x,
                                                const int* __restrict__ perm) {
    int i = blockIdx.x * 256 + threadIdx.x;
    if (i >= NB * FD / 4) return;
    int b  = i >> 10;
    int k4 = (i & 1023) << 2;
    int p  = __ldg(perm + k4);
    const float4 v = *(const float4*)(x + (long long)b * FD + p);
    __half2* dst = (__half2*)(g_xperm + (long long)b * FD + k4);
    dst[0] = __floats2half2_rn(v.x, v.y);
    dst[1] = __floats2half2_rn(v.z, v.w);
}

__global__ void __launch_bounds__(256) k_prep_w(const float* __restrict__ wu,
                                                const float* __restrict__ wd) {
    int i = blockIdx.x * 256 + threadIdx.x;
    const int N4 = NH * HI * HO / 4;
    if (i >= N4) return;
    float4 a = *(const float4*)(wu + (long long)i * 4);
    __half2* d1 = (__half2*)(g_w1 + (long long)i * 4);
    d1[0] = __floats2half2_rn(a.x, a.y);
    d1[1] = __floats2half2_rn(a.z, a.w);
    float4 b = *(const float4*)(wd + (long long)i * 4);
    __half2* d2 = (__half2*)(g_w2 + (long long)i * 4);
    d2[0] = __floats2half2_rn(b.x, b.y);
    d2[1] = __floats2half2_rn(b.z, b.w);
}

// ---------------------------------------------------------------------------
// k_up_res: GEMM1 with B-resident smem + M-loop.
// CTA = (head, n-tile of 128). B = W1[h][:,n0:n0+128] (256x128 fp16 = 64 KB)
// loaded ONCE. Then 8 row-blocks x 4 K-tiles = 32 A-tiles (16 KB each) stream
// through a 3-stage cp.async pipeline, prefetch distance 2 (issued after the
// barrier). Warp tile 32x64 (8 warps 4x2), 2 CTAs/SM.
// Epilogue per row-block: gelu(acc + b_up) -> g_h fp16.
// ---------------------------------------------------------------------------
__global__ void __launch_bounds__(256, 2) k_up_res(const float* __restrict__ bias) {
    extern __shared__ char smem[];
    constexpr int ASTG = 128 * 128;        // 16 KB per A stage
    constexpr int TOT  = 32;               // 8 blocks * 4 k-tiles
    const unsigned sAb = (unsigned)__cvta_generic_to_shared(smem);
    const unsigned sBb = sAb + 3 * ASTG;   // B: 256 rows x 256 B = 64 KB

    const int h  = blockIdx.x >> 3;
    const int nt = blockIdx.x & 7;
    const int n0 = nt << 7;
    const long long R0 = (long long)blockIdx.y << 10;   // 1024 rows per CTA
    const int tid = threadIdx.x;
    const int lane = tid & 31, warp = tid >> 5;
    const int wm = warp & 3, wn = warp >> 2;

    const __half* Ag = g_xperm + R0 * FD + h * HI;
    const __half* Bg = g_w1 + (long long)h * HI * HO + n0;

    // B load (once): 256 k-rows x 128 n (trans layout rows=k, 256 B each)
#pragma unroll
    for (int i = 0; i < 16; i++) {
        int c = tid + i * 256;
        int k = c >> 4, cn = c & 15;
        CP16(sBb + k * 256 + ((cn ^ ((k & 7) << 1)) << 4),
             Bg + (long long)k * HO + cn * 8);
    }
    asm volatile("cp.async.commit_group;\n");

    auto load_A = [&](int stage, int s) {
        const unsigned sa = sAb + stage * ASTG;
        const __half* Ak = Ag + (long long)((s >> 2) * 128) * FD + (s & 3) * 64;
#pragma unroll
        for (int i = 0; i < 4; i++) {
            int c = tid + i * 256;
            int m = c >> 3, g = c & 7;
            CP16(sa + m * 128 + ((g ^ (m & 7)) << 4), Ak + (long long)m * FD + g * 8);
        }
        asm volatile("cp.async.commit_group;\n");
    };

    load_A(0, 0);
    load_A(1, 1);

    float acc[2][8][4] = {};
    const int g = lane >> 2, t = lane & 3;
    const int cb = h * HO + n0;

    for (int s = 0; s < TOT; s++) {
        if (s + 1 < TOT) asm volatile("cp.async.wait_group 1;\n");
        else             asm volatile("cp.async.wait_group 0;\n");
        __syncthreads();
        if (s + 2 < TOT) load_A((s + 2) % 3, s + 2);

        const unsigned sa = sAb + (s % 3) * ASTG;
        const int kb = (s & 3) * 64;
#pragma unroll
        for (int ks = 0; ks < 4; ks++) {
            const int k16 = ks * 2 + (lane >> 4);
            unsigned af[2][4];
#pragma unroll
            for (int mi = 0; mi < 2; mi++) {
                int m = wm * 32 + mi * 16 + (lane & 15);
                ldsm4(af[mi][0], af[mi][1], af[mi][2], af[mi][3],
                      sa + m * 128 + ((k16 ^ (m & 7)) << 4));
            }
            unsigned bf[8][2];
#pragma unroll
            for (int nj = 0; nj < 4; nj++) {
                int k = kb + ks * 16 + (lane & 15);
                int cn = wn * 8 + nj * 2 + (lane >> 4);
                unsigned t0, t1, t2, t3;
                ldsm4t(t0, t1, t2, t3, sBb + k * 256 + ((cn ^ ((k & 7) << 1)) << 4));
                bf[nj * 2][0] = t0; bf[nj * 2][1] = t1;
                bf[nj * 2 + 1][0] = t2; bf[nj * 2 + 1][1] = t3;
            }
#pragma unroll
            for (int mi = 0; mi < 2; mi++)
#pragma unroll
                for (int ni = 0; ni < 8; ni++)
                    mma16816(acc[mi][ni], af[mi], bf[ni]);
        }

        if ((s & 3) == 3) {
            // Epilogue for row-block s>>2 (no smem touched; overlaps prefetch)
            const long long r0 = R0 + (long long)(s >> 2) * 128;
#pragma unroll
            for (int mi = 0; mi < 2; mi++) {
#pragma unroll
                for (int ni = 0; ni < 8; ni++) {
                    long long r = r0 + wm * 32 + mi * 16 + g;
                    int c = cb + wn * 64 + ni * 8 + t * 2;
                    float b0 = __ldg(bias + c), b1 = __ldg(bias + c + 1);
                    float v0 = gelu_f(acc[mi][ni][0] + b0);
                    float v1 = gelu_f(acc[mi][ni][1] + b1);
                    *(__half2*)(g_h + r * MD + c) = __floats2half2_rn(v0, v1);
                    v0 = gelu_f(acc[mi][ni][2] + b0);
                    v1 = gelu_f(acc[mi][ni][3] + b1);
                    *(__half2*)(g_h + (r + 8) * MD + c) = __floats2half2_rn(v0, v1);
                    acc[mi][ni][0] = acc[mi][ni][1] = acc[mi][ni][2] = acc[mi][ni][3] = 0.f;
                }
            }
        }
    }
}

// ---------------------------------------------------------------------------
// k_down: exact R8 golden kernel (BM=128, BN=128, BK=64, 8 warps 4x2,
// 3-stage cp.async, XOR swizzle, trans-ldmatrix B, scatter epilogue).
// ---------------------------------------------------------------------------
__global__ void __launch_bounds__(256, 2) k_down(const float* __restrict__ bias,
                                                 const int* __restrict__ perm,
                                                 float* __restrict__ out) {
    constexpr int KT = 16;
    extern __shared__ char smem[];
    constexpr int ASTG = 128 * 128;
    constexpr int BSTG = 64 * 256;
    const unsigned sAb = (unsigned)__cvta_generic_to_shared(smem);
    const unsigned sBb = sAb + 3 * ASTG;

    const int h  = blockIdx.x >> 1;
    const int nt = blockIdx.x & 1;
    const int r0 = blockIdx.y << 7;
    const int n0 = nt << 7;
    const int tid = threadIdx.x;
    const int lane = tid & 31, warp = tid >> 5;
    const int wm = warp & 3, wn = warp >> 2;

    const __half* Ag = g_h + (long long)r0 * MD + h * HO;
    const __half* Bg = g_w2 + (long long)h * HO * HI + n0;

    auto load_stage = [&](int stage, int kt) {
        const unsigned sa = sAb + stage * ASTG;
        const unsigned sb = sBb + stage * BSTG;
        const __half* Agk = Ag + kt * 64;
        const __half* Bgk = Bg + (long long)kt * 64 * HI;
#pragma unroll
        for (int i = 0; i < 4; i++) {
            int c = tid + i * 256;
            int m = c >> 3, g = c & 7;
            CP16(sa + m * 128 + ((g ^ (m & 7)) << 4), Agk + (long long)m * MD + g * 8);
        }
#pragma unroll
        for (int i = 0; i < 4; i++) {
            int c = tid + i * 256;
            int k = c >> 4, cn = c & 15;
            CP16(sb + k * 256 + ((cn ^ ((k & 7) << 1)) << 4), Bgk + (long long)k * HI + cn * 8);
        }
        asm volatile("cp.async.commit_group;\n");
    };

    float acc[2][8][4] = {};

    load_stage(0, 0);

    for (int kt = 0; kt < KT; kt++) {
        if (kt + 1 < KT) {
            load_stage((kt + 1) % 3, kt + 1);
            asm volatile("cp.async.wait_group 1;\n");
        } else {
            asm volatile("cp.async.wait_group 0;\n");
        }
        __syncthreads();
        const int stg = kt % 3;
        const unsigned sa = sAb + stg * ASTG;
        const unsigned sb = sBb + stg * BSTG;
#pragma unroll
        for (int ks = 0; ks < 4; ks++) {
            const int k16 = ks * 2 + (lane >> 4);
            unsigned af[2][4];
#pragma unroll
            for (int mi = 0; mi < 2; mi++) {
                int m = wm * 32 + mi * 16 + (lane & 15);
                ldsm4(af[mi][0], af[mi][1], af[mi][2], af[mi][3],
                      sa + m * 128 + ((k16 ^ (m & 7)) << 4));
            }
            unsigned bf[8][2];
#pragma unroll
            for (int nj = 0; nj < 4; nj++) {
                int k = ks * 16 + (lane & 15);
                int cn = wn * 8 + nj * 2 + (lane >> 4);
                unsigned t0, t1, t2, t3;
                ldsm4t(t0, t1, t2, t3, sb + k * 256 + ((cn ^ ((k & 7) << 1)) << 4));
                bf[nj * 2][0] = t0; bf[nj * 2][1] = t1;
                bf[nj * 2 + 1][0] = t2; bf[nj * 2 + 1][1] = t3;
            }
#pragma unroll
            for (int mi = 0; mi < 2; mi++)
#pragma unroll
                for (int ni = 0; ni < 8; ni++)
                    mma16816(acc[mi][ni], af[mi], bf[ni]);
        }
    }

    const int g = lane >> 2, t = lane & 3;
    const int cb = h * HI + n0;
#pragma unroll
    for (int mi = 0; mi < 2; mi++) {
#pragma unroll
        for (int ni = 0; ni < 8; ni++) {
            int r = r0 + wm * 32 + mi * 16 + g;
            int c = cb + wn * 64 + ni * 8 + t * 2;
            float b0 = __ldg(bias + c), b1 = __ldg(bias + c + 1);
            int p = __ldg(perm + c);   // c even; 64-chunk perm => perm[c+1]=perm[c]+1
            float2 o0; o0.x = acc[mi][ni][0] + b0; o0.y = acc[mi][ni][1] + b1;
            *(float2*)(out + (long long)r * FD + p) = o0;
            float2 o1; o1.x = acc[mi][ni][2] + b0; o1.y = acc[mi][ni][3] + b1;
            *(float2*)(out + (long long)(r + 8) * FD + p) = o1;
        }
    }
}

extern "C" void kernel_launch(void* const* d_in, const int* in_sizes, int n_in,
                              void* d_out, int out_size) {
    const float* x      = (const float*)d_in[0];
    const int*   perm   = (const int*)d_in[1];
    const float* w_up   = (const float*)d_in[2];
    const float* b_up   = (const float*)d_in[3];
    const float* w_down = (const float*)d_in[4];
    const float* b_down = (const float*)d_in[5];
    float* out = (float*)d_out;

    k_prep_x<<<(NB * FD / 4 + 255) / 256, 256>>>(x, perm);
    k_prep_w<<<(NH * HI * HO / 4 + 255) / 256, 256>>>(w_up, w_down);

    constexpr int SMEM_UP = 3 * (128 * 128) + 256 * 256;   // 49152 + 65536 = 114688
    constexpr int SMEM_DN = 3 * (128 * 128 + 64 * 256);    // 98304
    cudaFuncSetAttribute(k_up_res, cudaFuncAttributeMaxDynamicSharedMemorySize, SMEM_UP);
    cudaFuncSetAttribute(k_down,  cudaFuncAttributeMaxDynamicSharedMemorySize, SMEM_DN);

    dim3 g1(NH * 8, 8);          // (128, 8): 1024 rows per CTA
    k_up_res<<<g1, 256, SMEM_UP>>>(b_up);

    dim3 g2(NH * 2, NB / 128);   // (32, 64)
    k_down<<<g2, 256, SMEM_DN>>>(b_down, perm, out);
}